// round 1
// baseline (speedup 1.0000x reference)
#include <cuda_runtime.h>

#define D      1024
#define LSEQ   2048
#define BATCH  2
#define NH     16
#define DH     64
#define MTOT   (BATCH*LSEQ)

// Scratch (allocation-free rule: __device__ globals)
__device__ float g_q [MTOT*D];
__device__ float g_k [MTOT*D];
__device__ float g_v [MTOT*D];
__device__ float g_ao[MTOT*D];

// ---------------------------------------------------------------------------
// NT SGEMM: C[M,1024] = A[M,1024] * W[1024,1024]^T (+bias), M = 4096
// 128x128 tile, BK=16, 256 threads, 8x8 per thread.
// ---------------------------------------------------------------------------
#define AP 132   // smem pitch (floats): 16-byte aligned, reduces store conflicts

__global__ void __launch_bounds__(256) gemm_nt(const float* __restrict__ A,
                                               const float* __restrict__ W,
                                               const float* __restrict__ bias,
                                               float* __restrict__ C)
{
    __shared__ float As[16 * AP];   // As[k][m]
    __shared__ float Bs[16 * AP];   // Bs[k][n]
    const int m0 = blockIdx.y * 128;
    const int n0 = blockIdx.x * 128;
    const int tid = threadIdx.x;
    const int ty = tid >> 4;        // 0..15 -> row group
    const int tx = tid & 15;        // 0..15 -> col group

    float acc[8][8];
#pragma unroll
    for (int i = 0; i < 8; i++)
#pragma unroll
        for (int j = 0; j < 8; j++) acc[i][j] = 0.f;

    for (int k0 = 0; k0 < D; k0 += 16) {
#pragma unroll
        for (int t = 0; t < 2; ++t) {
            int v   = tid + t * 256;          // 0..511
            int row = v >> 2;                 // 0..127
            int c4  = (v & 3) * 4;            // 0,4,8,12
            float4 a = *(const float4*)(A + (size_t)(m0 + row) * D + k0 + c4);
            As[(c4 + 0) * AP + row] = a.x;
            As[(c4 + 1) * AP + row] = a.y;
            As[(c4 + 2) * AP + row] = a.z;
            As[(c4 + 3) * AP + row] = a.w;
            float4 b = *(const float4*)(W + (size_t)(n0 + row) * D + k0 + c4);
            Bs[(c4 + 0) * AP + row] = b.x;
            Bs[(c4 + 1) * AP + row] = b.y;
            Bs[(c4 + 2) * AP + row] = b.z;
            Bs[(c4 + 3) * AP + row] = b.w;
        }
        __syncthreads();

#pragma unroll
        for (int kk = 0; kk < 16; kk++) {
            float a[8], b[8];
            *(float4*)&a[0] = *(float4*)&As[kk * AP + ty * 8];
            *(float4*)&a[4] = *(float4*)&As[kk * AP + ty * 8 + 4];
            *(float4*)&b[0] = *(float4*)&Bs[kk * AP + tx * 8];
            *(float4*)&b[4] = *(float4*)&Bs[kk * AP + tx * 8 + 4];
#pragma unroll
            for (int i = 0; i < 8; i++)
#pragma unroll
                for (int j = 0; j < 8; j++)
                    acc[i][j] += a[i] * b[j];
        }
        __syncthreads();
    }

#pragma unroll
    for (int i = 0; i < 8; i++) {
        int row = m0 + ty * 8 + i;
#pragma unroll
        for (int j4 = 0; j4 < 8; j4 += 4) {
            int col = n0 + tx * 8 + j4;
            float4 r;
            r.x = acc[i][j4 + 0];
            r.y = acc[i][j4 + 1];
            r.z = acc[i][j4 + 2];
            r.w = acc[i][j4 + 3];
            if (bias) {
                r.x += bias[col + 0];
                r.y += bias[col + 1];
                r.z += bias[col + 2];
                r.w += bias[col + 3];
            }
            *(float4*)(C + (size_t)row * D + col) = r;
        }
    }
}

// ---------------------------------------------------------------------------
// Sliding-window attention. Block = (batch b, head h, 64-query tile).
// Window for query i covers keys [i-32, i+31]; out-of-range keys contribute
// score 0 (exactly matching reference: zero-padded x -> zero k rows) and v=0.
// Thread (q, s): s in 0..3, handles window slots j = s + 4*t, t=0..15 for QK,
// and output dims [16s, 16s+16) for PV.
// ---------------------------------------------------------------------------
#define QP 68                    // smem pitch (floats)
#define ATTN_SMEM ((64*QP + 128*QP + 128*QP + 64*QP) * 4)   // 104448 bytes

__global__ void __launch_bounds__(256) attn_kernel()
{
    extern __shared__ float smem[];
    float* Qs = smem;                 // [64][QP]  q rows
    float* Ks = Qs + 64 * QP;         // [128][QP] key rows (local key kl -> global qstart-32+kl)
    float* Vs = Ks + 128 * QP;        // [128][QP]
    float* Ps = Vs + 128 * QP;        // [64][QP]  probs

    const int qstart = blockIdx.x * 64;
    const int h      = blockIdx.y;
    const int b      = blockIdx.z;
    const int tid    = threadIdx.x;

    // Load Q tile: 64 rows x 64 dims
#pragma unroll
    for (int t = 0; t < 4; t++) {
        int v  = tid + t * 256;
        int q  = v >> 4;
        int d4 = (v & 15) * 4;
        float4 val = *(const float4*)(g_q + (size_t)(b * LSEQ + qstart + q) * D + h * DH + d4);
        *(float4*)&Qs[q * QP + d4] = val;
    }
    // Load K/V: 128 key rows (zero-fill out of range)
#pragma unroll
    for (int t = 0; t < 8; t++) {
        int v  = tid + t * 256;
        int kl = v >> 4;
        int d4 = (v & 15) * 4;
        int kg = qstart - 32 + kl;
        float4 kv = make_float4(0.f, 0.f, 0.f, 0.f);
        float4 vv = make_float4(0.f, 0.f, 0.f, 0.f);
        if (kg >= 0 && kg < LSEQ) {
            size_t off = (size_t)(b * LSEQ + kg) * D + h * DH + d4;
            kv = *(const float4*)(g_k + off);
            vv = *(const float4*)(g_v + off);
        }
        *(float4*)&Ks[kl * QP + d4] = kv;
        *(float4*)&Vs[kl * QP + d4] = vv;
    }
    __syncthreads();

    const int q = tid >> 2;      // 0..63
    const int s = tid & 3;       // 0..3

    // ---- QK^T for window slots j = s + 4t ----
    float sc[16];
#pragma unroll
    for (int t = 0; t < 16; t++) sc[t] = 0.f;

    for (int dc = 0; dc < DH; dc += 4) {
        float4 qv = *(float4*)&Qs[q * QP + dc];
#pragma unroll
        for (int t = 0; t < 16; t++) {
            int key = q + s + 4 * t;                  // local key index = q + j
            float4 kv = *(float4*)&Ks[key * QP + dc];
            sc[t] += qv.x * kv.x + qv.y * kv.y + qv.z * kv.z + qv.w * kv.w;
        }
    }

    // ---- softmax over 64 window slots (4 lanes per query share) ----
    float mx = -1e30f;
#pragma unroll
    for (int t = 0; t < 16; t++) {
        sc[t] *= 0.125f;                              // 1/sqrt(64)
        mx = fmaxf(mx, sc[t]);
    }
    mx = fmaxf(mx, __shfl_xor_sync(0xffffffffu, mx, 1));
    mx = fmaxf(mx, __shfl_xor_sync(0xffffffffu, mx, 2));
    float sum = 0.f;
#pragma unroll
    for (int t = 0; t < 16; t++) {
        sc[t] = __expf(sc[t] - mx);
        sum += sc[t];
    }
    sum += __shfl_xor_sync(0xffffffffu, sum, 1);
    sum += __shfl_xor_sync(0xffffffffu, sum, 2);
    float inv = 1.f / sum;
#pragma unroll
    for (int t = 0; t < 16; t++)
        Ps[q * QP + s + 4 * t] = sc[t] * inv;
    __syncthreads();

    // ---- PV: thread (q,s) computes out dims [16s, 16s+16) ----
    float4 a0 = make_float4(0.f, 0.f, 0.f, 0.f);
    float4 a1 = a0, a2 = a0, a3 = a0;
#pragma unroll 4
    for (int j = 0; j < 64; j++) {
        float p = Ps[q * QP + j];
        const float* vr = &Vs[(q + j) * QP + s * 16];
        float4 v0 = *(const float4*)(vr + 0);
        float4 v1 = *(const float4*)(vr + 4);
        float4 v2 = *(const float4*)(vr + 8);
        float4 v3 = *(const float4*)(vr + 12);
        a0.x += p * v0.x; a0.y += p * v0.y; a0.z += p * v0.z; a0.w += p * v0.w;
        a1.x += p * v1.x; a1.y += p * v1.y; a1.z += p * v1.z; a1.w += p * v1.w;
        a2.x += p * v2.x; a2.y += p * v2.y; a2.z += p * v2.z; a2.w += p * v2.w;
        a3.x += p * v3.x; a3.y += p * v3.y; a3.z += p * v3.z; a3.w += p * v3.w;
    }
    float* outp = g_ao + (size_t)(b * LSEQ + qstart + q) * D + h * DH + s * 16;
    *(float4*)(outp + 0)  = a0;
    *(float4*)(outp + 4)  = a1;
    *(float4*)(outp + 8)  = a2;
    *(float4*)(outp + 12) = a3;
}

// ---------------------------------------------------------------------------
extern "C" void kernel_launch(void* const* d_in, const int* in_sizes, int n_in,
                              void* d_out, int out_size)
{
    const float* x  = (const float*)d_in[0];
    const float* Wq = (const float*)d_in[1];
    const float* Wk = (const float*)d_in[2];
    const float* Wv = (const float*)d_in[3];
    const float* Wo = (const float*)d_in[4];
    const float* bo = (const float*)d_in[5];
    float* out = (float*)d_out;

    float *qp, *kp, *vp, *aop;
    cudaGetSymbolAddress((void**)&qp,  g_q);
    cudaGetSymbolAddress((void**)&kp,  g_k);
    cudaGetSymbolAddress((void**)&vp,  g_v);
    cudaGetSymbolAddress((void**)&aop, g_ao);

    dim3 gg(D / 128, MTOT / 128);   // (8, 32)

    gemm_nt<<<gg, 256>>>(x, Wq, nullptr, qp);
    gemm_nt<<<gg, 256>>>(x, Wk, nullptr, kp);
    gemm_nt<<<gg, 256>>>(x, Wv, nullptr, vp);

    cudaFuncSetAttribute(attn_kernel, cudaFuncAttributeMaxDynamicSharedMemorySize, ATTN_SMEM);
    attn_kernel<<<dim3(LSEQ / 64, NH, BATCH), 256, ATTN_SMEM>>>();

    gemm_nt<<<gg, 256>>>(aop, Wo, bo, out);
}

// round 5
// speedup vs baseline: 1.8039x; 1.8039x over previous
#include <cuda_runtime.h>
#include <cstdint>

#define D      1024
#define LSEQ   2048
#define BATCH  2
#define NH     16
#define DH     64
#define MTOT   (BATCH*LSEQ)

// Scratch (allocation-free rule: __device__ globals)
__device__ float g_q [MTOT*D];
__device__ float g_k [MTOT*D];
__device__ float g_v [MTOT*D];
__device__ float g_ao[MTOT*D];

__device__ __forceinline__ uint32_t cvt_tf32(float f) {
    uint32_t o;
    asm("cvt.rna.tf32.f32 %0, %1;" : "=r"(o) : "f"(f));
    return o;
}

__device__ __forceinline__ void mma_tf32(float* c,
                                         uint32_t a0, uint32_t a1, uint32_t a2, uint32_t a3,
                                         uint32_t b0, uint32_t b1) {
    asm volatile(
        "mma.sync.aligned.m16n8k8.row.col.f32.tf32.tf32.f32 "
        "{%0,%1,%2,%3}, {%4,%5,%6,%7}, {%8,%9}, {%0,%1,%2,%3};\n"
        : "+f"(c[0]), "+f"(c[1]), "+f"(c[2]), "+f"(c[3])
        : "r"(a0), "r"(a1), "r"(a2), "r"(a3), "r"(b0), "r"(b1));
}

// ===========================================================================
// TF32 mma.sync GEMM: C[M,1024] = A[M,1024] * W[1024,1024]^T (+bias)
// CTA tile 128x128, BK=32, 256 threads (8 warps, warp tile 32x64).
// Smem stores k-permuted rows: p(k) = (k&3)*8 + ((k&4)?4:0) + (k>>3), pitch 36.
// Thread (g=lane>>2, tig=lane&3) fetches a whole 4-kstep fragment group with
// one lds.128 at [row][tig*8] / [row][tig*8+4] (conflict-free with pitch 36).
// ===========================================================================
#define PITCH 36
#define TSZ   (128 * PITCH)            // floats per buffer
#define GEMM_SMEM (4 * TSZ * 4)        // As[2] + Bs[2] = 73728 bytes

__global__ void __launch_bounds__(256, 1) gemm_mma(const float* __restrict__ A,
                                                   const float* __restrict__ W,
                                                   const float* __restrict__ bias,
                                                   float* __restrict__ C)
{
    extern __shared__ float sm[];
    float* As = sm;              // As[buf][128][36]
    float* Bs = sm + 2 * TSZ;    // Bs[buf][128][36]

    const int tid = threadIdx.x;
    const int m0 = blockIdx.y * 128;
    const int n0 = blockIdx.x * 128;

    const int wid    = tid >> 5;
    const int lane   = tid & 31;
    const int warp_m = wid & 3;          // 0..3 -> 32-row slab
    const int warp_n = wid >> 2;         // 0..1 -> 64-col slab
    const int g      = lane >> 2;        // groupID 0..7
    const int tig    = lane & 3;         // thread-in-group 0..3

    // ---- global load mapping: 4 float4 per thread per matrix per chunk ----
    int lrow[4], lbase[4];
    const float* Ap[4];
    const float* Bp[4];
#pragma unroll
    for (int j = 0; j < 4; j++) {
        int idx = tid + j * 256;         // 0..1023
        int row = idx >> 3;              // 0..127
        int c4  = (idx & 7) * 4;         // k offset 0,4,..28
        lrow[j]  = row;
        lbase[j] = row * PITCH + ((c4 & 4) ? 4 : 0) + (c4 >> 3);
        Ap[j] = A + (size_t)(m0 + row) * D + c4;
        Bp[j] = W + (size_t)(n0 + row) * D + c4;
    }

    float acc[2][8][4];
#pragma unroll
    for (int mt = 0; mt < 2; mt++)
#pragma unroll
        for (int nt = 0; nt < 8; nt++)
#pragma unroll
            for (int r = 0; r < 4; r++) acc[mt][nt][r] = 0.f;

    float4 ra[4], rb[4];

    // ---- prologue: chunk 0 -> buf 0; prefetch chunk 1 ----
#pragma unroll
    for (int j = 0; j < 4; j++) { ra[j] = *(const float4*)(Ap[j]); rb[j] = *(const float4*)(Bp[j]); }
#pragma unroll
    for (int j = 0; j < 4; j++) {
        float* a = As + lbase[j];
        a[0]  = __uint_as_float(cvt_tf32(ra[j].x));
        a[8]  = __uint_as_float(cvt_tf32(ra[j].y));
        a[16] = __uint_as_float(cvt_tf32(ra[j].z));
        a[24] = __uint_as_float(cvt_tf32(ra[j].w));
        float* b = Bs + lbase[j];
        b[0]  = __uint_as_float(cvt_tf32(rb[j].x));
        b[8]  = __uint_as_float(cvt_tf32(rb[j].y));
        b[16] = __uint_as_float(cvt_tf32(rb[j].z));
        b[24] = __uint_as_float(cvt_tf32(rb[j].w));
    }
#pragma unroll
    for (int j = 0; j < 4; j++) { ra[j] = *(const float4*)(Ap[j] + 32); rb[j] = *(const float4*)(Bp[j] + 32); }
    __syncthreads();

    for (int i = 0; i < 32; i++) {
        const int buf = i & 1;

        // store prefetched chunk i+1 into the other buffer
        if (i + 1 < 32) {
            float* Asb = As + ((i + 1) & 1) * TSZ;
            float* Bsb = Bs + ((i + 1) & 1) * TSZ;
#pragma unroll
            for (int j = 0; j < 4; j++) {
                float* a = Asb + lbase[j];
                a[0]  = __uint_as_float(cvt_tf32(ra[j].x));
                a[8]  = __uint_as_float(cvt_tf32(ra[j].y));
                a[16] = __uint_as_float(cvt_tf32(ra[j].z));
                a[24] = __uint_as_float(cvt_tf32(ra[j].w));
                float* b = Bsb + lbase[j];
                b[0]  = __uint_as_float(cvt_tf32(rb[j].x));
                b[8]  = __uint_as_float(cvt_tf32(rb[j].y));
                b[16] = __uint_as_float(cvt_tf32(rb[j].z));
                b[24] = __uint_as_float(cvt_tf32(rb[j].w));
            }
        }
        // kick off loads for chunk i+2
        if (i + 2 < 32) {
            const int koff = (i + 2) * 32;
#pragma unroll
            for (int j = 0; j < 4; j++) { ra[j] = *(const float4*)(Ap[j] + koff); rb[j] = *(const float4*)(Bp[j] + koff); }
        }

        // ---- compute chunk i from buf ----
        const float* Asb = As + buf * TSZ;
        const float* Bsb = Bs + buf * TSZ;

        uint32_t af[2][4][4];   // [mt][areg 0..3][kstep]
#pragma unroll
        for (int mt = 0; mt < 2; mt++) {
            int r = warp_m * 32 + mt * 16 + g;
            float4 t0 = *(const float4*)&Asb[r * PITCH + tig * 8];           // a0, ks0..3
            float4 t1 = *(const float4*)&Asb[r * PITCH + tig * 8 + 4];       // a2
            float4 t2 = *(const float4*)&Asb[(r + 8) * PITCH + tig * 8];     // a1
            float4 t3 = *(const float4*)&Asb[(r + 8) * PITCH + tig * 8 + 4]; // a3
            af[mt][0][0] = __float_as_uint(t0.x); af[mt][0][1] = __float_as_uint(t0.y);
            af[mt][0][2] = __float_as_uint(t0.z); af[mt][0][3] = __float_as_uint(t0.w);
            af[mt][1][0] = __float_as_uint(t2.x); af[mt][1][1] = __float_as_uint(t2.y);
            af[mt][1][2] = __float_as_uint(t2.z); af[mt][1][3] = __float_as_uint(t2.w);
            af[mt][2][0] = __float_as_uint(t1.x); af[mt][2][1] = __float_as_uint(t1.y);
            af[mt][2][2] = __float_as_uint(t1.z); af[mt][2][3] = __float_as_uint(t1.w);
            af[mt][3][0] = __float_as_uint(t3.x); af[mt][3][1] = __float_as_uint(t3.y);
            af[mt][3][2] = __float_as_uint(t3.z); af[mt][3][3] = __float_as_uint(t3.w);
        }

#pragma unroll
        for (int nt = 0; nt < 8; nt++) {
            int n = warp_n * 64 + nt * 8 + g;
            float4 u0 = *(const float4*)&Bsb[n * PITCH + tig * 8];      // b0, ks0..3
            float4 u1 = *(const float4*)&Bsb[n * PITCH + tig * 8 + 4];  // b1
            uint32_t b0[4] = { __float_as_uint(u0.x), __float_as_uint(u0.y),
                               __float_as_uint(u0.z), __float_as_uint(u0.w) };
            uint32_t b1[4] = { __float_as_uint(u1.x), __float_as_uint(u1.y),
                               __float_as_uint(u1.z), __float_as_uint(u1.w) };
#pragma unroll
            for (int mt = 0; mt < 2; mt++)
#pragma unroll
                for (int ks = 0; ks < 4; ks++)
                    mma_tf32(acc[mt][nt],
                             af[mt][0][ks], af[mt][1][ks], af[mt][2][ks], af[mt][3][ks],
                             b0[ks], b1[ks]);
        }
        __syncthreads();
    }

    // ---- epilogue ----
#pragma unroll
    for (int mt = 0; mt < 2; mt++) {
        int row = m0 + warp_m * 32 + mt * 16 + g;
#pragma unroll
        for (int nt = 0; nt < 8; nt++) {
            int col = n0 + warp_n * 64 + nt * 8 + 2 * tig;
            float bx = 0.f, by = 0.f;
            if (bias) { bx = bias[col]; by = bias[col + 1]; }
            float2 v0 = make_float2(acc[mt][nt][0] + bx, acc[mt][nt][1] + by);
            float2 v1 = make_float2(acc[mt][nt][2] + bx, acc[mt][nt][3] + by);
            *(float2*)(C + (size_t)row * D + col)       = v0;
            *(float2*)(C + (size_t)(row + 8) * D + col) = v1;
        }
    }
}

// ---------------------------------------------------------------------------
// Sliding-window attention (unchanged, 106us)
// ---------------------------------------------------------------------------
#define QP 68
#define ATTN_SMEM ((64*QP + 128*QP + 128*QP + 64*QP) * 4)

__global__ void __launch_bounds__(256) attn_kernel()
{
    extern __shared__ float fsmem[];
    float* Qs = fsmem;
    float* Ks = Qs + 64 * QP;
    float* Vs = Ks + 128 * QP;
    float* Ps = Vs + 128 * QP;

    const int qstart = blockIdx.x * 64;
    const int h      = blockIdx.y;
    const int b      = blockIdx.z;
    const int tid    = threadIdx.x;

#pragma unroll
    for (int t = 0; t < 4; t++) {
        int v  = tid + t * 256;
        int q  = v >> 4;
        int d4 = (v & 15) * 4;
        float4 val = *(const float4*)(g_q + (size_t)(b * LSEQ + qstart + q) * D + h * DH + d4);
        *(float4*)&Qs[q * QP + d4] = val;
    }
#pragma unroll
    for (int t = 0; t < 8; t++) {
        int v  = tid + t * 256;
        int kl = v >> 4;
        int d4 = (v & 15) * 4;
        int kg = qstart - 32 + kl;
        float4 kv = make_float4(0.f, 0.f, 0.f, 0.f);
        float4 vv = make_float4(0.f, 0.f, 0.f, 0.f);
        if (kg >= 0 && kg < LSEQ) {
            size_t off = (size_t)(b * LSEQ + kg) * D + h * DH + d4;
            kv = *(const float4*)(g_k + off);
            vv = *(const float4*)(g_v + off);
        }
        *(float4*)&Ks[kl * QP + d4] = kv;
        *(float4*)&Vs[kl * QP + d4] = vv;
    }
    __syncthreads();

    const int q = tid >> 2;
    const int s = tid & 3;

    float sc[16];
#pragma unroll
    for (int t = 0; t < 16; t++) sc[t] = 0.f;

    for (int dc = 0; dc < DH; dc += 4) {
        float4 qv = *(float4*)&Qs[q * QP + dc];
#pragma unroll
        for (int t = 0; t < 16; t++) {
            int key = q + s + 4 * t;
            float4 kv = *(float4*)&Ks[key * QP + dc];
            sc[t] += qv.x * kv.x + qv.y * kv.y + qv.z * kv.z + qv.w * kv.w;
        }
    }

    float mx = -1e30f;
#pragma unroll
    for (int t = 0; t < 16; t++) {
        sc[t] *= 0.125f;
        mx = fmaxf(mx, sc[t]);
    }
    mx = fmaxf(mx, __shfl_xor_sync(0xffffffffu, mx, 1));
    mx = fmaxf(mx, __shfl_xor_sync(0xffffffffu, mx, 2));
    float sum = 0.f;
#pragma unroll
    for (int t = 0; t < 16; t++) {
        sc[t] = __expf(sc[t] - mx);
        sum += sc[t];
    }
    sum += __shfl_xor_sync(0xffffffffu, sum, 1);
    sum += __shfl_xor_sync(0xffffffffu, sum, 2);
    float inv = 1.f / sum;
#pragma unroll
    for (int t = 0; t < 16; t++)
        Ps[q * QP + s + 4 * t] = sc[t] * inv;
    __syncthreads();

    float4 a0 = make_float4(0.f, 0.f, 0.f, 0.f);
    float4 a1 = a0, a2 = a0, a3 = a0;
#pragma unroll 4
    for (int j = 0; j < 64; j++) {
        float p = Ps[q * QP + j];
        const float* vr = &Vs[(q + j) * QP + s * 16];
        float4 v0 = *(const float4*)(vr + 0);
        float4 v1 = *(const float4*)(vr + 4);
        float4 v2 = *(const float4*)(vr + 8);
        float4 v3 = *(const float4*)(vr + 12);
        a0.x += p * v0.x; a0.y += p * v0.y; a0.z += p * v0.z; a0.w += p * v0.w;
        a1.x += p * v1.x; a1.y += p * v1.y; a1.z += p * v1.z; a1.w += p * v1.w;
        a2.x += p * v2.x; a2.y += p * v2.y; a2.z += p * v2.z; a2.w += p * v2.w;
        a3.x += p * v3.x; a3.y += p * v3.y; a3.z += p * v3.z; a3.w += p * v3.w;
    }
    float* outp = g_ao + (size_t)(b * LSEQ + qstart + q) * D + h * DH + s * 16;
    *(float4*)(outp + 0)  = a0;
    *(float4*)(outp + 4)  = a1;
    *(float4*)(outp + 8)  = a2;
    *(float4*)(outp + 12) = a3;
}

// ---------------------------------------------------------------------------
extern "C" void kernel_launch(void* const* d_in, const int* in_sizes, int n_in,
                              void* d_out, int out_size)
{
    const float* x  = (const float*)d_in[0];
    const float* Wq = (const float*)d_in[1];
    const float* Wk = (const float*)d_in[2];
    const float* Wv = (const float*)d_in[3];
    const float* Wo = (const float*)d_in[4];
    const float* bo = (const float*)d_in[5];
    float* out = (float*)d_out;

    float *qp, *kp, *vp, *aop;
    cudaGetSymbolAddress((void**)&qp,  g_q);
    cudaGetSymbolAddress((void**)&kp,  g_k);
    cudaGetSymbolAddress((void**)&vp,  g_v);
    cudaGetSymbolAddress((void**)&aop, g_ao);

    cudaFuncSetAttribute(gemm_mma, cudaFuncAttributeMaxDynamicSharedMemorySize, GEMM_SMEM);
    cudaFuncSetAttribute(attn_kernel, cudaFuncAttributeMaxDynamicSharedMemorySize, ATTN_SMEM);

    dim3 gg(D / 128, MTOT / 128);   // (8, 32) = 256 CTAs

    gemm_mma<<<gg, 256, GEMM_SMEM>>>(x, Wq, nullptr, qp);
    gemm_mma<<<gg, 256, GEMM_SMEM>>>(x, Wk, nullptr, kp);
    gemm_mma<<<gg, 256, GEMM_SMEM>>>(x, Wv, nullptr, vp);

    attn_kernel<<<dim3(LSEQ / 64, NH, BATCH), 256, ATTN_SMEM>>>();

    gemm_mma<<<gg, 256, GEMM_SMEM>>>(aop, Wo, bo, out);
}